// round 17
// baseline (speedup 1.0000x reference)
#include <cuda_runtime.h>
#include <cuda_fp16.h>
#include <cstdint>

// VectorQuantizer: z [32,256,64,64] f32, emb [1024,256] f32
// out = concat( z_q [32,256,64,64] f32 , idx [131072] f32 )
//
// R17 = R16 (540us champion) with repair's scan restructured:
//   phase1: 4x LDG.128/lane + pure HMIN2 tree (no index tracking)
//   phase2: register re-scan, flag d<=b1+EPS, count+min-index;
//           count==1 -> done, else exact chains (R4-verified bit-exact).
// mma/esq/convB/scatter byte-identical to R16.

#define N_TOK   131072
#define KDIM    256
#define NEMB    1024
#define CH_STRIDE 4096
#define B_STRIDE  (256*4096)
#define EPS 3e-3f

__device__ float  g_esq[NEMB];
__device__ __half g_Bh[NEMB * KDIM];                 // 512 KB fp16 emb
__device__ __half g_dist[(size_t)N_TOK * NEMB];      // 256 MB approx distances
__device__ int    g_idx[N_TOK];

// ---- SMEM layout (dynamic) ----
#define SA_H 0          // A hi: 256 k-rows x 128 tok fp16 (swizzled)  64KB
#define SB   65536      // B double buffer: 2 x 16KB                   32KB
#define SESQ 98304      // esq 4KB
#define SM_TOTAL 102400

__device__ __forceinline__ uint32_t smem_u32(const void* p) {
    uint32_t a;
    asm("{ .reg .u64 t; cvta.to.shared.u64 t, %1; cvt.u32.u64 %0, t; }" : "=r"(a) : "l"(p));
    return a;
}
__device__ __forceinline__ void ldsm4(uint32_t* r, uint32_t a) {
    asm volatile("ldmatrix.sync.aligned.m8n8.x4.shared.b16 {%0,%1,%2,%3}, [%4];"
                 : "=r"(r[0]), "=r"(r[1]), "=r"(r[2]), "=r"(r[3]) : "r"(a));
}
__device__ __forceinline__ void ldsm4t(uint32_t* r, uint32_t a) {
    asm volatile("ldmatrix.sync.aligned.m8n8.x4.trans.shared.b16 {%0,%1,%2,%3}, [%4];"
                 : "=r"(r[0]), "=r"(r[1]), "=r"(r[2]), "=r"(r[3]) : "r"(a));
}
__device__ __forceinline__ void mma16816(float* c, const uint32_t* a, const uint32_t* b) {
    asm volatile("mma.sync.aligned.m16n8k16.row.col.f32.f16.f16.f32 "
                 "{%0,%1,%2,%3}, {%4,%5,%6,%7}, {%8,%9}, {%0,%1,%2,%3};"
                 : "+f"(c[0]), "+f"(c[1]), "+f"(c[2]), "+f"(c[3])
                 : "r"(a[0]), "r"(a[1]), "r"(a[2]), "r"(a[3]), "r"(b[0]), "r"(b[1]));
}
#define CP_COMMIT() asm volatile("cp.async.commit_group;" ::: "memory")
#define CP_WAIT1()  asm volatile("cp.async.wait_group 1;" ::: "memory")
#define CP_WAIT0()  asm volatile("cp.async.wait_group 0;" ::: "memory")

// ======================= Kernel: esq (exact, XLA order) ====================
__global__ void esq_kernel(const float* __restrict__ emb) {
    int warp = (blockIdx.x * blockDim.x + threadIdx.x) >> 5;
    int lane = threadIdx.x & 31;
    if (warp >= NEMB) return;
    const float* row = emb + (size_t)warp * KDIM;
    float s = 0.f;
#pragma unroll
    for (int c = lane; c < KDIM; c += 32) {
        float v = row[c];
        s = __fadd_rn(s, __fmul_rn(v, v));
    }
#pragma unroll
    for (int o = 16; o; o >>= 1)
        s = __fadd_rn(s, __shfl_xor_sync(0xffffffffu, s, o));
    if (lane == 0) g_esq[warp] = s;
}

// ======================= Kernel: convert emb -> fp16 =======================
__global__ void convB_kernel(const float* __restrict__ emb) {
    int i = (blockIdx.x * 256 + threadIdx.x) * 4;
    float4 v = *(const float4*)(emb + i);
    __half2 a = __floats2half2_rn(v.x, v.y);
    __half2 b = __floats2half2_rn(v.z, v.w);
    *(uint2*)(g_Bh + i) = make_uint2(*(uint32_t*)&a, *(uint32_t*)&b);
}

// ======================= Kernel: mma.sync GEMM + d-store ===================
__device__ __forceinline__ void issueB(uint32_t smem_base, int cc, int tid) {
#pragma unroll
    for (int j = 0; j < 4; j++) {
        int idx = tid + j * 256;          // 0..1023 16B granules
        int n = idx >> 5;                 // row within chunk 0..31
        int c = idx & 31;                 // 16B col within row
        const char* src = (const char*)g_Bh + (size_t)(cc * 32 + n) * 512 + (size_t)c * 16;
        uint32_t dst = smem_base + SB + (uint32_t)((cc & 1) * 16384
                     + n * 512 + ((c ^ (n & 7)) << 4));
        asm volatile("cp.async.cg.shared.global [%0], [%1], 16;" :: "r"(dst), "l"(src) : "memory");
    }
    CP_COMMIT();
}

__global__ __launch_bounds__(256, 2)
void mma_kernel(const float* __restrict__ z) {
    extern __shared__ char smem[];
    const uint32_t smem_base = smem_u32(smem);
    const int tid  = threadIdx.x;
    const int lane = tid & 31;
    const int wid  = tid >> 5;
    const int n0   = blockIdx.x * 128;
    const int b    = n0 >> 12;
    const int hw0  = n0 & 4095;
    const float* zbase = z + (size_t)b * B_STRIDE + hw0;

    float* esq_s = (float*)(smem + SESQ);

    // prefetch first two B chunks
    issueB(smem_base, 0, tid);
    issueB(smem_base, 1, tid);

    for (int i = tid; i < NEMB; i += 256) esq_s[i] = g_esq[i];

    // ---- convert A: z fp32 -> fp16 hi, k-major swizzled smem ----
#pragma unroll
    for (int it = 0; it < 16; it++) {
        int g  = tid + it * 256;          // granule 0..4095
        int c  = g >> 4;                  // channel (k)
        int gt = g & 15;                  // token granule (8 tokens)
        const float* src = zbase + (size_t)c * CH_STRIDE + gt * 8;
        float4 v0 = *(const float4*)(src);
        float4 v1 = *(const float4*)(src + 4);
        __half2 h0 = __floats2half2_rn(v0.x, v0.y);
        __half2 h1 = __floats2half2_rn(v0.z, v0.w);
        __half2 h2 = __floats2half2_rn(v1.x, v1.y);
        __half2 h3 = __floats2half2_rn(v1.z, v1.w);
        uint32_t ph[4] = {*(uint32_t*)&h0, *(uint32_t*)&h1, *(uint32_t*)&h2, *(uint32_t*)&h3};
        uint32_t off = (uint32_t)c * 256 + (uint32_t)((gt ^ (c & 7)) << 4);
        *(uint4*)(smem + SA_H + off) = *(uint4*)ph;
    }

    // ---- per-lane ldmatrix address bases ----
    const int l7  = lane & 7;
    const int lt1 = (lane >> 3) & 1;
    const int lt2 = (lane >> 4) & 1;
    const int M0  = wid * 16;
    const uint32_t aoff = (uint32_t)(lt2 * 8 + l7) * 256
                        + (uint32_t)((((M0 >> 3) + lt1) ^ l7) << 4);
    const uint32_t addrAh = smem_base + SA_H + aoff;

    const int gID = lane >> 2;
    const int tIG = lane & 3;

    __syncthreads();   // A + esq ready

    // ---- load ALL A fragments into registers (chunk-invariant) ----
    uint32_t Ah[16][4];
#pragma unroll
    for (int kk = 0; kk < 16; kk++)
        ldsm4t(Ah[kk], addrAh + (uint32_t)kk * 4096);

    // d-store row bases: this thread owns token rows (M0+gID) and (M0+gID+8)
    __half* drow0 = g_dist + (size_t)(n0 + M0 + gID) * NEMB;
    __half* drow1 = drow0 + (size_t)8 * NEMB;

    for (int ec = 0; ec < 32; ec++) {
        if (ec < 31) { CP_WAIT1(); } else { CP_WAIT0(); }
        __syncthreads();
        const uint32_t bufb = smem_base + SB + (uint32_t)((ec & 1) * 16384);
        const uint32_t brow0 = bufb + (uint32_t)((lt2 * 8 + l7) * 512);        // codes 0..15
        const uint32_t brow1 = bufb + (uint32_t)(((16 + lt2 * 8 + l7)) * 512); // codes 16..31

        float acc[4][4];
#pragma unroll
        for (int t = 0; t < 4; t++)
#pragma unroll
            for (int r = 0; r < 4; r++) acc[t][r] = 0.f;

#pragma unroll
        for (int kk = 0; kk < 16; kk++) {
            const uint32_t kchunk = (uint32_t)(kk * 2) + (uint32_t)lt1;
            const uint32_t sw = ((kchunk ^ (uint32_t)l7) << 4);
            uint32_t bh0[4], bh1[4];
            ldsm4(bh0, brow0 + sw);
            ldsm4(bh1, brow1 + sw);
            mma16816(acc[0], Ah[kk], &bh0[0]);
            mma16816(acc[1], Ah[kk], &bh0[2]);
            mma16816(acc[2], Ah[kk], &bh1[0]);
            mma16816(acc[3], Ah[kk], &bh1[2]);
        }

        // ---- d = esq - 2*dot, store row-major as fp16 (cols e0, e0+1) ----
#pragma unroll
        for (int t = 0; t < 4; t++) {
            int e0 = ec * 32 + t * 8 + tIG * 2;   // 0..1022, half2-aligned
            float2 e2 = *(const float2*)&esq_s[e0];
            __half2 h0 = __floats2half2_rn(__fmaf_rn(-2.0f, acc[t][0], e2.x),
                                           __fmaf_rn(-2.0f, acc[t][1], e2.y));
            __half2 h1 = __floats2half2_rn(__fmaf_rn(-2.0f, acc[t][2], e2.x),
                                           __fmaf_rn(-2.0f, acc[t][3], e2.y));
            *(__half2*)(drow0 + e0) = h0;
            *(__half2*)(drow1 + e0) = h1;
        }
        __syncthreads();
        if (ec < 30) issueB(smem_base, ec + 2, tid);
    }
}

// ======================= Kernel: repair (warp per token) ===================
// phase1: HMIN2 tree over 4x LDG.128 -> warp min b1 (no index).
// phase2: register re-scan: flag d<=b1+EPS, count + min flagged index.
//   count==1 -> unambiguous (same gate as b2 > b1+EPS), write idx.
//   else gather flagged -> exact chains (bit-exact R4-verified arithmetic).
__global__ __launch_bounds__(256)
void repair_kernel(const float* __restrict__ z, const float* __restrict__ emb) {
    __shared__ short cands[8][64];
    __shared__ int   ccnt[8];
    const int wl   = threadIdx.x >> 5;
    const int lane = threadIdx.x & 31;
    const int n = blockIdx.x * 8 + wl;
    const uint4* drow4 = (const uint4*)(g_dist + (size_t)n * NEMB);

    // ---- phase 1: load row (4x uint4 = 32 halves/lane), HMIN2 tree ----
    uint4 q[4];
#pragma unroll
    for (int j = 0; j < 4; j++) q[j] = drow4[lane + 32 * j];

    __half2 m2 = __halves2half2(__ushort_as_half(0x7C00), __ushort_as_half(0x7C00)); // +inf
#pragma unroll
    for (int j = 0; j < 4; j++) {
        const __half2* h = (const __half2*)&q[j];
        m2 = __hmin2(m2, __hmin2(__hmin2(h[0], h[1]), __hmin2(h[2], h[3])));
    }
    float b1 = fminf(__low2float(m2), __high2float(m2));
#pragma unroll
    for (int o = 16; o; o >>= 1)
        b1 = fminf(b1, __shfl_xor_sync(0xffffffffu, b1, o));
    const float thresh = b1 + EPS;

    // ---- phase 2: register re-scan: count + min flagged index ----
    int cnt = 0, idx = 0x7fffffff;
#pragma unroll
    for (int j = 0; j < 4; j++) {
        const __half2* h = (const __half2*)&q[j];
#pragma unroll
        for (int k = 0; k < 4; k++) {
            float2 f = __half22float2(h[k]);
            int e = 8 * (lane + 32 * j) + 2 * k;
            if (f.x <= thresh) { cnt++; idx = min(idx, e); }
            if (f.y <= thresh) { cnt++; idx = min(idx, e + 1); }
        }
    }
#pragma unroll
    for (int o = 16; o; o >>= 1) {
        cnt += __shfl_xor_sync(0xffffffffu, cnt, o);
        idx  = min(idx, __shfl_xor_sync(0xffffffffu, idx, o));
    }
    if (cnt == 1) {
        if (lane == 0) g_idx[n] = idx;
        return;
    }

    // ---- ambiguous: gather flagged candidates ----
    if (lane == 0) ccnt[wl] = 0;
    __syncwarp();
#pragma unroll
    for (int j = 0; j < 4; j++) {
        const __half2* h = (const __half2*)&q[j];
#pragma unroll
        for (int k = 0; k < 4; k++) {
            float2 f = __half22float2(h[k]);
            int e = 8 * (lane + 32 * j) + 2 * k;
            if (f.x <= thresh) {
                int p = atomicAdd(&ccnt[wl], 1);
                if (p < 64) cands[wl][p] = (short)e;
            }
            if (f.y <= thresh) {
                int p = atomicAdd(&ccnt[wl], 1);
                if (p < 64) cands[wl][p] = (short)(e + 1);
            }
        }
    }
    __syncwarp();
    int total = ccnt[wl];
    int full = (total > 64);
    int ncand = full ? NEMB : total;

    const int b = n >> 12, hw = n & 4095;
    const float* zb = z + (size_t)b * B_STRIDE + hw;

    // z_sq: XLA row-reduce order (lane-strided c = lane+32i, unfused, xor tree)
    float s = 0.f;
#pragma unroll
    for (int i = 0; i < 8; i++) {
        float v = zb[(size_t)(lane + 32 * i) * CH_STRIDE];
        s = __fadd_rn(s, __fmul_rn(v, v));
    }
#pragma unroll
    for (int o = 16; o; o >>= 1)
        s = __fadd_rn(s, __shfl_xor_sync(0xffffffffu, s, o));
    float zsq = s;

    // exact chains, lane-strided over candidates
    float m = 3.0e38f; int mi = 0x7fffffff;
    for (int base = 0; base < ncand; base += 32) {
        int j = base + lane;
        if (j < ncand) {
            int e = full ? j : (int)cands[wl][j];
            const float* er = emb + (size_t)e * KDIM;
            float acc = 0.f;
#pragma unroll 8
            for (int c = 0; c < KDIM; c++)
                acc = __fmaf_rn(zb[(size_t)c * CH_STRIDE], er[c], acc);
            float A = __fadd_rn(zsq, g_esq[e]);
            float d = __fsub_rn(A, __fmul_rn(2.0f, acc));
            if (d < m || (d == m && e < mi)) { m = d; mi = e; }
        }
    }
#pragma unroll
    for (int o = 16; o; o >>= 1) {
        float om = __shfl_xor_sync(0xffffffffu, m, o);
        int   oi = __shfl_xor_sync(0xffffffffu, mi, o);
        if (om < m || (om == m && oi < mi)) { m = om; mi = oi; }
    }
    if (lane == 0) g_idx[n] = mi;
}

// ======================= Kernel: gather/scatter ============================
__global__ __launch_bounds__(256)
void scatter_kernel(const float* __restrict__ emb, float* __restrict__ out,
                    float* __restrict__ out_idx, int write_idx) {
    const int tid = threadIdx.x;
    const int n0 = blockIdx.x * 128;
    const int b = n0 >> 12, hw0 = n0 & 4095;
    float* obase = out + (size_t)b * B_STRIDE + hw0;
    const int tok = tid & 127;
    const int half = tid >> 7;
    const int myidx = g_idx[n0 + tok];
    if (tid < 128 && write_idx) out_idx[n0 + tid] = (float)g_idx[n0 + tid];
    const float* erow = emb + (size_t)myidx * KDIM;
#pragma unroll 4
    for (int c = half; c < KDIM; c += 2)
        obase[(size_t)c * CH_STRIDE + tok] = erow[c];
}

// ---------------------------------------------------------------------------
extern "C" void kernel_launch(void* const* d_in, const int* in_sizes, int n_in,
                              void* d_out, int out_size) {
    const float* z   = (const float*)d_in[0];
    const float* emb = (const float*)d_in[1];
    float* out = (float*)d_out;

    const int zq_elems = 32 * 256 * 64 * 64;
    int write_idx = (out_size >= zq_elems + N_TOK) ? 1 : 0;

    cudaFuncSetAttribute(mma_kernel, cudaFuncAttributeMaxDynamicSharedMemorySize, SM_TOTAL);

    esq_kernel<<<128, 256>>>(emb);
    convB_kernel<<<256, 256>>>(emb);
    mma_kernel<<<N_TOK / 128, 256, SM_TOTAL>>>(z);
    repair_kernel<<<N_TOK / 8, 256>>>(z, emb);
    scatter_kernel<<<N_TOK / 128, 256>>>(emb, out, out + zq_elems, write_idx);
}